// round 13
// baseline (speedup 1.0000x reference)
#include <cuda_runtime.h>

// SuperpixelPooling: out[b,l,c] = mean over pixels p with label[b,p]==l of x[b,c,p]
// x: [B, C, H, W] float32, labels: [B, 1, H, W] int64 (or int32), out: [B, L, C] f32
//
// Per-CTA counting sort of a pixel tile by label; per 4-channel group, stage
// values in smem as AoS float4 (XOR-swizzled) and emit ONE red.global.add.v4
// per label-run. Register-prefetch software pipeline overlaps next cg's LDGs
// with the gather. R12: TPX 4096->2048 so smem=49KB + prefetch=32 regs allow
// 4 CTAs/SM (occ 2x->4x warps), single wave at 512 CTAs.

#define BB 4
#define CC 128
#define HWP (512 * 512)
#define LL 512
#define TPX 2048                 // pixels per CTA tile
#define NT 256                   // threads per CTA
#define RWIN (TPX / NT)          // 8 sorted positions per thread
#define NCHUNK (TPX / 4 / NT)    // 2 float4 chunks per thread per plane

__device__ int g_cnt[BB * LL];   // per (b, label) pixel counts
__device__ int g_is64;           // 1 if labels are int64, 0 if int32

// swizzle for AoS float4 stage: e&7 permutes within each 8-lane STS.128 phase
__device__ __forceinline__ int swz(int px) { return px ^ ((px >> 3) & 7); }

// ---------------------------------------------------------------------------
// Detect label dtype: int64 labels < 512 have all odd 32-bit words == 0.
// ---------------------------------------------------------------------------
__global__ void detect_kernel(const unsigned* __restrict__ lab32) {
    __shared__ int any;
    if (threadIdx.x == 0) any = 0;
    __syncthreads();
    int found = 0;
    for (int i = threadIdx.x; i < 4096; i += blockDim.x)
        if (lab32[2 * i + 1] != 0u) found = 1;
    if (found) atomicOr(&any, 1);
    __syncthreads();
    if (threadIdx.x == 0) g_is64 = any ? 0 : 1;
}

__device__ __forceinline__ int get_label(const unsigned* __restrict__ lab32,
                                         long p, int is64) {
    return (is64 ? (int)lab32[2 * p] : (int)lab32[p]) & (LL - 1);
}

__global__ void zero_out_kernel(float4* __restrict__ out) {
    int i = blockIdx.x * blockDim.x + threadIdx.x;   // 65536 float4
    out[i] = make_float4(0.f, 0.f, 0.f, 0.f);
}

__global__ void zero_cnt_kernel() {
    int i = blockIdx.x * blockDim.x + threadIdx.x;
    if (i < BB * LL) g_cnt[i] = 0;
}

__device__ __forceinline__ void red4(float* a, float v0, float v1, float v2, float v3) {
    asm volatile("red.global.add.v4.f32 [%0], {%1, %2, %3, %4};"
                 :: "l"(a), "f"(v0), "f"(v1), "f"(v2), "f"(v3)
                 : "memory");
}

// ---------------------------------------------------------------------------
// Main pooling kernel. Grid: (HWP/TPX = 128, BB), block NT=256, target 4 CTA/SM.
// Dynamic smem (50176 B):
//   stage : TPX float4 AoS (4 channels), swizzled              32768 B
//   spixT : TPX u32, sorted (label<<16)|px, TRANSPOSED layout   8192 B
//   lab16 : TPX u16                                             4096 B
//   hist/ofs/scan                                               5120 B
// ---------------------------------------------------------------------------
extern __shared__ char smem_raw[];

__global__ void __launch_bounds__(NT, 4)
pool_kernel(const float* __restrict__ x, const unsigned* __restrict__ lab32,
            float* __restrict__ out) {
    float4*         stage = (float4*)smem_raw;
    unsigned*       spixT = (unsigned*)(smem_raw + TPX * 16);
    unsigned short* lab16 = (unsigned short*)((char*)spixT + TPX * 4);
    int*            hist  = (int*)((char*)lab16 + TPX * 2);
    int*            ofs   = hist + LL;
    int*            scan  = ofs + LL;

    const int t = threadIdx.x;
    const int b = blockIdx.y;
    const long tile_base = (long)blockIdx.x * TPX;
    const int is64 = g_is64;

    // ---- 1. labels + histogram ----
    for (int i = t; i < LL; i += NT) hist[i] = 0;
    __syncthreads();
    #pragma unroll
    for (int j = 0; j < RWIN; j++) {
        int i = t + j * NT;
        int l = get_label(lab32, (long)b * HWP + tile_base + i, is64);
        lab16[i] = (unsigned short)l;
        atomicAdd(&hist[l], 1);
    }
    __syncthreads();

    // counts -> global (tile partial)
    for (int i = t; i < LL; i += NT) {
        int h = hist[i];
        if (h) atomicAdd(&g_cnt[b * LL + i], h);
    }

    // ---- 2. exclusive scan of hist into ofs (pair per thread) ----
    int h0 = hist[2 * t], h1 = hist[2 * t + 1];
    int ps = h0 + h1;
    scan[t] = ps;
    __syncthreads();
    for (int d = 1; d < NT; d <<= 1) {
        int v = (t >= d) ? scan[t - d] : 0;
        __syncthreads();
        scan[t] += v;
        __syncthreads();
    }
    int excl = scan[t] - ps;
    ofs[2 * t] = excl;
    ofs[2 * t + 1] = excl + h0;
    __syncthreads();

    // ---- 3. scatter sorted pairs into TRANSPOSED layout:
    //        sorted position p lives at spixT[(p%8)*256 + p/8]
    //        so the gather at step j reads spixT[j*256 + t] (lane-contiguous).
    #pragma unroll
    for (int j = 0; j < RWIN; j++) {
        int i = t + j * NT;
        int l = lab16[i];
        int pos = atomicAdd(&ofs[l], 1);
        spixT[((pos & (RWIN - 1)) << 8) | (pos >> 3)] =
            ((unsigned)l << 16) | (unsigned)i;
    }

    // ---- 4. per 4-channel group: software-pipelined stage + run-merge ----
    const float4* xb4 = (const float4*)(x + (long)b * CC * HWP + tile_base);
    const long PLANE4 = HWP / 4;               // float4 per channel plane
    float* ob = out + (long)b * LL * CC;

    // prefetch registers for one full cg (4 planes x 2 chunks = 32 regs)
    float4 ra[NCHUNK], rb[NCHUNK], rc[NCHUNK], rd[NCHUNK];

    // prologue: load cg = 0
    {
        const float4* p0 = xb4;
        #pragma unroll
        for (int k = 0; k < NCHUNK; k++) {
            int f = k * NT + t;
            ra[k] = p0[f + 0 * PLANE4];
            rb[k] = p0[f + 1 * PLANE4];
            rc[k] = p0[f + 2 * PLANE4];
            rd[k] = p0[f + 3 * PLANE4];
        }
    }

    for (int cg = 0; cg < CC / 4; cg++) {
        __syncthreads();        // stage free (prev gather done); also covers sort
        // STS: register 4x4 transpose into swizzled AoS float4
        #pragma unroll
        for (int k = 0; k < NCHUNK; k++) {
            int px = 4 * (k * NT + t);
            stage[swz(px + 0)] = make_float4(ra[k].x, rb[k].x, rc[k].x, rd[k].x);
            stage[swz(px + 1)] = make_float4(ra[k].y, rb[k].y, rc[k].y, rd[k].y);
            stage[swz(px + 2)] = make_float4(ra[k].z, rb[k].z, rc[k].z, rd[k].z);
            stage[swz(px + 3)] = make_float4(ra[k].w, rb[k].w, rc[k].w, rd[k].w);
        }
        // prefetch next cg: LDGs in flight during the whole gather below
        if (cg + 1 < CC / 4) {
            const float4* p0 = xb4 + (long)(cg + 1) * 4 * PLANE4;
            #pragma unroll
            for (int k = 0; k < NCHUNK; k++) {
                int f = k * NT + t;
                ra[k] = p0[f + 0 * PLANE4];
                rb[k] = p0[f + 1 * PLANE4];
                rc[k] = p0[f + 2 * PLANE4];
                rd[k] = p0[f + 3 * PLANE4];
            }
        }
        __syncthreads();        // stage ready

        // walk this thread's contiguous sorted window [t*8, t*8+8)
        float a0 = 0.f, a1 = 0.f, a2 = 0.f, a3 = 0.f;
        int cur = -1;
        #pragma unroll
        for (int j = 0; j < RWIN; j++) {
            unsigned sp = spixT[j * NT + t];            // conflict-free
            int l  = (int)(sp >> 16);
            int px = (int)(sp & 0xFFFFu);
            float4 v = stage[swz(px)];                  // single LDS.128
            if (l != cur) {
                if (cur >= 0) red4(ob + (long)cur * CC + cg * 4, a0, a1, a2, a3);
                cur = l; a0 = v.x; a1 = v.y; a2 = v.z; a3 = v.w;
            } else {
                a0 += v.x; a1 += v.y; a2 += v.z; a3 += v.w;
            }
        }
        red4(ob + (long)cur * CC + cg * 4, a0, a1, a2, a3);
    }
}

// ---------------------------------------------------------------------------
// Normalize in place (vectorized): out[b,l,c] /= max(count[b,l], 1)
// ---------------------------------------------------------------------------
__global__ void norm_kernel(float4* __restrict__ out) {
    int i = blockIdx.x * blockDim.x + threadIdx.x;   // 65536 float4
    float inv = 1.0f / fmaxf((float)g_cnt[i / (CC / 4)], 1.0f);
    float4 v = out[i];
    v.x *= inv; v.y *= inv; v.z *= inv; v.w *= inv;
    out[i] = v;
}

extern "C" void kernel_launch(void* const* d_in, const int* in_sizes, int n_in,
                              void* d_out, int out_size) {
    const float* x = (const float*)d_in[0];
    const unsigned* lab32 = (const unsigned*)d_in[1];
    float* out = (float*)d_out;

    static const int SMEM_BYTES =
        TPX * 16 + TPX * 4 + TPX * 2 + LL * 4 + LL * 4 + NT * 4;  // 50176

    cudaFuncSetAttribute(pool_kernel,
                         cudaFuncAttributeMaxDynamicSharedMemorySize, SMEM_BYTES);

    int nv4 = BB * LL * CC / 4;   // 65536 float4

    // launch order chosen so pool_kernel is the 4th launch (ncu capture slot)
    detect_kernel<<<1, 256>>>(lab32);
    zero_out_kernel<<<nv4 / 256, 256>>>((float4*)out);
    zero_cnt_kernel<<<(BB * LL + 255) / 256, 256>>>();

    dim3 grid(HWP / TPX, BB);
    pool_kernel<<<grid, NT, SMEM_BYTES>>>(x, lab32, out);

    norm_kernel<<<nv4 / 256, 256>>>((float4*)out);
}

// round 17
// speedup vs baseline: 1.2215x; 1.2215x over previous
#include <cuda_runtime.h>

// SuperpixelPooling: out[b,l,c] = mean over pixels p with label[b,p]==l of x[b,c,p]
// x: [B, C, H, W] float32, labels: [B, 1, H, W] int64 (or int32), out: [B, L, C] f32
//
// Per-CTA counting sort of a 4096-pixel tile by label; per 4-channel group,
// stage values in smem as AoS float4 (XOR-swizzled) and emit ONE
// red.global.add.v4 per label-run. Register-prefetch pipeline overlaps next
// cg's LDGs with the gather. R14: NT 256->512 at TPX=4096 — 32 warps/SM at
// occ 2 WITHOUT shortening label runs (R13 showed runs/atomics, not occ,
// dominate when tile shrinks).

#define BB 4
#define CC 128
#define HWP (512 * 512)
#define LL 512
#define TPX 4096                 // pixels per CTA tile
#define NT 512                   // threads per CTA
#define RWIN (TPX / NT)          // 8 sorted positions per thread
#define NCHUNK (TPX / 4 / NT)    // 2 float4 chunks per thread per plane

__device__ int g_cnt[BB * LL];   // per (b, label) pixel counts
__device__ int g_is64;           // 1 if labels are int64, 0 if int32

// swizzle for AoS float4 stage: e&7 permutes within each 8-lane STS.128 phase
__device__ __forceinline__ int swz(int px) { return px ^ ((px >> 3) & 7); }

// ---------------------------------------------------------------------------
// Detect label dtype: int64 labels < 512 have all odd 32-bit words == 0.
// ---------------------------------------------------------------------------
__global__ void detect_kernel(const unsigned* __restrict__ lab32) {
    __shared__ int any;
    if (threadIdx.x == 0) any = 0;
    __syncthreads();
    int found = 0;
    for (int i = threadIdx.x; i < 4096; i += blockDim.x)
        if (lab32[2 * i + 1] != 0u) found = 1;
    if (found) atomicOr(&any, 1);
    __syncthreads();
    if (threadIdx.x == 0) g_is64 = any ? 0 : 1;
}

__device__ __forceinline__ int get_label(const unsigned* __restrict__ lab32,
                                         long p, int is64) {
    return (is64 ? (int)lab32[2 * p] : (int)lab32[p]) & (LL - 1);
}

__global__ void zero_out_kernel(float4* __restrict__ out) {
    int i = blockIdx.x * blockDim.x + threadIdx.x;   // 65536 float4
    out[i] = make_float4(0.f, 0.f, 0.f, 0.f);
}

__global__ void zero_cnt_kernel() {
    int i = blockIdx.x * blockDim.x + threadIdx.x;
    if (i < BB * LL) g_cnt[i] = 0;
}

__device__ __forceinline__ void red4(float* a, float v0, float v1, float v2, float v3) {
    asm volatile("red.global.add.v4.f32 [%0], {%1, %2, %3, %4};"
                 :: "l"(a), "f"(v0), "f"(v1), "f"(v2), "f"(v3)
                 : "memory");
}

// ---------------------------------------------------------------------------
// Main pooling kernel. Grid: (HWP/TPX = 64, BB), block NT=512, occ 2/SM
// (32 warps). Dynamic smem (96256 B):
//   stage : TPX float4 AoS (4 channels), swizzled              65536 B
//   spixT : TPX u32, sorted (label<<16)|px, TRANSPOSED layout  16384 B
//   lab16 : TPX u16                                             8192 B
//   hist/ofs/scan (LL,LL,NT ints)                               6144 B
// ---------------------------------------------------------------------------
extern __shared__ char smem_raw[];

__global__ void __launch_bounds__(NT, 2)
pool_kernel(const float* __restrict__ x, const unsigned* __restrict__ lab32,
            float* __restrict__ out) {
    float4*         stage = (float4*)smem_raw;
    unsigned*       spixT = (unsigned*)(smem_raw + TPX * 16);
    unsigned short* lab16 = (unsigned short*)((char*)spixT + TPX * 4);
    int*            hist  = (int*)((char*)lab16 + TPX * 2);
    int*            ofs   = hist + LL;
    int*            scan  = ofs + LL;

    const int t = threadIdx.x;
    const int b = blockIdx.y;
    const long tile_base = (long)blockIdx.x * TPX;
    const int is64 = g_is64;

    // ---- 1. labels + histogram ----
    for (int i = t; i < LL; i += NT) hist[i] = 0;
    __syncthreads();
    #pragma unroll
    for (int j = 0; j < RWIN; j++) {
        int i = t + j * NT;
        int l = get_label(lab32, (long)b * HWP + tile_base + i, is64);
        lab16[i] = (unsigned short)l;
        atomicAdd(&hist[l], 1);
    }
    __syncthreads();

    // counts -> global (tile partial)
    for (int i = t; i < LL; i += NT) {
        int h = hist[i];
        if (h) atomicAdd(&g_cnt[b * LL + i], h);
    }

    // ---- 2. exclusive scan of hist into ofs (one entry per thread, NT==LL) ----
    int h = hist[t];
    scan[t] = h;
    __syncthreads();
    for (int d = 1; d < NT; d <<= 1) {
        int v = (t >= d) ? scan[t - d] : 0;
        __syncthreads();
        scan[t] += v;
        __syncthreads();
    }
    ofs[t] = scan[t] - h;          // exclusive prefix
    __syncthreads();

    // ---- 3. scatter sorted pairs into TRANSPOSED layout:
    //        sorted position p lives at spixT[(p%8)*512 + p/8]
    //        so the gather at step j reads spixT[j*512 + t] (lane-contiguous).
    #pragma unroll
    for (int j = 0; j < RWIN; j++) {
        int i = t + j * NT;
        int l = lab16[i];
        int pos = atomicAdd(&ofs[l], 1);
        spixT[((pos & (RWIN - 1)) << 9) | (pos >> 3)] =
            ((unsigned)l << 16) | (unsigned)i;
    }

    // ---- 4. per 4-channel group: software-pipelined stage + run-merge ----
    const float4* xb4 = (const float4*)(x + (long)b * CC * HWP + tile_base);
    const long PLANE4 = HWP / 4;               // float4 per channel plane
    float* ob = out + (long)b * LL * CC;

    // prefetch registers for one full cg (4 planes x 2 chunks = 32 regs)
    float4 ra[NCHUNK], rb[NCHUNK], rc[NCHUNK], rd[NCHUNK];

    // prologue: load cg = 0
    {
        const float4* p0 = xb4;
        #pragma unroll
        for (int k = 0; k < NCHUNK; k++) {
            int f = k * NT + t;
            ra[k] = p0[f + 0 * PLANE4];
            rb[k] = p0[f + 1 * PLANE4];
            rc[k] = p0[f + 2 * PLANE4];
            rd[k] = p0[f + 3 * PLANE4];
        }
    }

    for (int cg = 0; cg < CC / 4; cg++) {
        __syncthreads();        // stage free (prev gather done); also covers sort
        // STS: register 4x4 transpose into swizzled AoS float4
        #pragma unroll
        for (int k = 0; k < NCHUNK; k++) {
            int px = 4 * (k * NT + t);
            stage[swz(px + 0)] = make_float4(ra[k].x, rb[k].x, rc[k].x, rd[k].x);
            stage[swz(px + 1)] = make_float4(ra[k].y, rb[k].y, rc[k].y, rd[k].y);
            stage[swz(px + 2)] = make_float4(ra[k].z, rb[k].z, rc[k].z, rd[k].z);
            stage[swz(px + 3)] = make_float4(ra[k].w, rb[k].w, rc[k].w, rd[k].w);
        }
        // prefetch next cg: LDGs in flight during the whole gather below
        if (cg + 1 < CC / 4) {
            const float4* p0 = xb4 + (long)(cg + 1) * 4 * PLANE4;
            #pragma unroll
            for (int k = 0; k < NCHUNK; k++) {
                int f = k * NT + t;
                ra[k] = p0[f + 0 * PLANE4];
                rb[k] = p0[f + 1 * PLANE4];
                rc[k] = p0[f + 2 * PLANE4];
                rd[k] = p0[f + 3 * PLANE4];
            }
        }
        __syncthreads();        // stage ready

        // walk this thread's contiguous sorted window [t*8, t*8+8)
        float a0 = 0.f, a1 = 0.f, a2 = 0.f, a3 = 0.f;
        int cur = -1;
        #pragma unroll
        for (int j = 0; j < RWIN; j++) {
            unsigned sp = spixT[j * NT + t];            // conflict-free
            int l  = (int)(sp >> 16);
            int px = (int)(sp & 0xFFFFu);
            float4 v = stage[swz(px)];                  // single LDS.128
            if (l != cur) {
                if (cur >= 0) red4(ob + (long)cur * CC + cg * 4, a0, a1, a2, a3);
                cur = l; a0 = v.x; a1 = v.y; a2 = v.z; a3 = v.w;
            } else {
                a0 += v.x; a1 += v.y; a2 += v.z; a3 += v.w;
            }
        }
        red4(ob + (long)cur * CC + cg * 4, a0, a1, a2, a3);
    }
}

// ---------------------------------------------------------------------------
// Normalize in place (vectorized): out[b,l,c] /= max(count[b,l], 1)
// ---------------------------------------------------------------------------
__global__ void norm_kernel(float4* __restrict__ out) {
    int i = blockIdx.x * blockDim.x + threadIdx.x;   // 65536 float4
    float inv = 1.0f / fmaxf((float)g_cnt[i / (CC / 4)], 1.0f);
    float4 v = out[i];
    v.x *= inv; v.y *= inv; v.z *= inv; v.w *= inv;
    out[i] = v;
}

extern "C" void kernel_launch(void* const* d_in, const int* in_sizes, int n_in,
                              void* d_out, int out_size) {
    const float* x = (const float*)d_in[0];
    const unsigned* lab32 = (const unsigned*)d_in[1];
    float* out = (float*)d_out;

    static const int SMEM_BYTES =
        TPX * 16 + TPX * 4 + TPX * 2 + LL * 4 + LL * 4 + NT * 4;  // 96256

    cudaFuncSetAttribute(pool_kernel,
                         cudaFuncAttributeMaxDynamicSharedMemorySize, SMEM_BYTES);

    int nv4 = BB * LL * CC / 4;   // 65536 float4

    // launch order chosen so pool_kernel is the 4th launch (ncu capture slot)
    detect_kernel<<<1, 256>>>(lab32);
    zero_out_kernel<<<nv4 / 256, 256>>>((float4*)out);
    zero_cnt_kernel<<<(BB * LL + 255) / 256, 256>>>();

    dim3 grid(HWP / TPX, BB);
    pool_kernel<<<grid, NT, SMEM_BYTES>>>(x, lab32, out);

    norm_kernel<<<nv4 / 256, 256>>>((float4*)out);
}